// round 16
// baseline (speedup 1.0000x reference)
#include <cuda_runtime.h>
#include <cstdint>

#define BB 512
#define TT 1024
#define CC 256
#define LL 64
#define SS 129          // 2*LL+1
#define SPL 5           // states per lane (32*5 = 160 >= 129, padded)
#define WROWS 8         // rows per memory window
#define NW (TT / WROWS) // 128 windows
#define RING 4          // ring depth in windows (32 KB SMEM)
#define WBYTES (WROWS * CC * 4)   // 8192 bytes per window
#define EPSF 1e-7f
#define LN2F 0.69314718055994530942f
#define FULLM 0xffffffffu

// acquire parity wait (spin on try_wait with HW sleep hint)
__device__ __forceinline__ void mbar_wait(uint32_t addr, uint32_t parity) {
    asm volatile(
        "{\n\t.reg .pred P;\n\t"
        "WAIT_%=:\n\t"
        "mbarrier.try_wait.parity.acquire.cta.shared::cta.b64 P, [%0], %1, 0x989680;\n\t"
        "@P bra.uni DONE_%=;\n\t"
        "bra.uni WAIT_%=;\n\t"
        "DONE_%=:\n\t}"
        :: "r"(addr), "r"(parity) : "memory");
}
__device__ __forceinline__ void mbar_init(uint32_t addr, uint32_t cnt) {
    asm volatile("mbarrier.init.shared.b64 [%0], %1;" :: "r"(addr), "r"(cnt) : "memory");
}
__device__ __forceinline__ void mbar_expect_tx(uint32_t addr, uint32_t bytes) {
    asm volatile("mbarrier.arrive.expect_tx.shared.b64 _, [%0], %1;"
                 :: "r"(addr), "r"(bytes) : "memory");
}
__device__ __forceinline__ void mbar_arrive(uint32_t addr) {
    asm volatile("mbarrier.arrive.shared.b64 _, [%0];" :: "r"(addr) : "memory");
}
__device__ __forceinline__ void bulk_g2s(uint32_t dst, const void* src, uint32_t bytes,
                                         uint32_t mbar) {
    asm volatile(
        "cp.async.bulk.shared::cluster.global.mbarrier::complete_tx::bytes [%0], [%1], %2, [%3];"
        :: "r"(dst), "l"(src), "r"(bytes), "r"(mbar) : "memory");
}

__global__ void __launch_bounds__(64)
ctc_warp_kernel(const int* __restrict__ y_true,
                const float* __restrict__ y_pred,
                float* __restrict__ out)
{
    __shared__ __align__(128) float ring[RING * WROWS * CC];   // 32 KB
    __shared__ unsigned long long full_mb[RING];
    __shared__ unsigned long long empty_mb[RING];

    const int b     = blockIdx.x;
    const int tid   = threadIdx.x;
    const int lane  = tid & 31;
    const int wrp   = tid >> 5;
    const int blank = CC - 1;

    const uint32_t ringa = (uint32_t)__cvta_generic_to_shared(&ring[0]);
    const uint32_t fmb   = (uint32_t)__cvta_generic_to_shared(&full_mb[0]);
    const uint32_t emb   = (uint32_t)__cvta_generic_to_shared(&empty_mb[0]);

    if (tid == 0) {
#pragma unroll
        for (int s = 0; s < RING; s++) {
            mbar_init(fmb + s * 8, 1);   // 1 arrival (the expect_tx) + tx bytes
            mbar_init(emb + s * 8, 1);   // 1 arrival (consumer lane 0)
        }
    }
    __syncthreads();    // barriers visible to all before any use

    if (wrp == 1) {
        // ============ producer: single elected thread, bulk copies only ============
        // Window v -> slot v%RING, full phase v/RING. Before re-arming a slot
        // (v >= RING), wait empty phase (v/RING - 1): consumer finished window
        // v-RING. <=1 phase in flight per mbarrier by construction.
        if (lane == 0) {
            const float* gsrc = y_pred + (size_t)b * (size_t)(TT * CC);
            for (int v = 0; v < NW; ++v) {
                const int s = v & (RING - 1);
                if (v >= RING)
                    mbar_wait(emb + s * 8, ((v >> 2) & 1) ^ 1);   // phase v/RING-1
                mbar_expect_tx(fmb + s * 8, WBYTES);
                bulk_g2s(ringa + s * WBYTES, gsrc + (size_t)v * WROWS * CC,
                         WBYTES, fmb + s * 8);
            }
        }
        return;
    }

    // ============ consumer warp: recursion only ============
    int   cls[SPL];
    float skf[SPL];     // 1 if skip (s-2 -> s) allowed, 0 otherwise
#pragma unroll
    for (int j = 0; j < SPL; j++) {
        int s = lane * SPL + j;
        int c = blank, c2 = blank;
        if (s < SS && (s & 1)) {
            c = y_true[b * LL + (s >> 1)];
            if (s >= 3) c2 = y_true[b * LL + (s >> 1) - 1];
        }
        cls[j] = c;
        skf[j] = (c != blank && c != c2) ? 1.0f : 0.0f;
    }

    // block-floating-point state: alpha = m * 2^E (per-lane frame)
    float m0 = 0.f, m1 = 0.f, m2 = 0.f, m3 = 0.f, m4 = 0.f;
    int   E  = 0;
    float P[WROWS][SPL];

#define GATHER(RB)                                                      \
    {                                                                   \
        const float* rb_ = (RB);                                        \
        _Pragma("unroll")                                               \
        for (int r = 0; r < WROWS; r++)                                 \
            _Pragma("unroll")                                           \
            for (int j = 0; j < SPL; j++)                               \
                P[r][j] = rb_[r * CC + cls[j]] + EPSF;                  \
    }

#define HALF(QS, QE)                                                    \
    {                                                                   \
        int nbE = __shfl_up_sync(FULLM, E, 1);                          \
        if (lane == 0) nbE = E;                                         \
        int d_ = nbE - E;                                               \
        d_ = d_ < -96 ? -96 : (d_ > 96 ? 96 : d_);                      \
        float sn = __int_as_float((d_ + 127) << 23);                    \
        if (lane == 0) sn = 0.0f;                                       \
        _Pragma("unroll")                                               \
        for (int q = (QS); q < (QE); ++q) {                             \
            float nb4 = __shfl_up_sync(FULLM, m4, 1);                   \
            float nb3 = __shfl_up_sync(FULLM, m3, 1);                   \
            float u1 = nb4 * sn;                                        \
            float u2 = nb3 * sn;                                        \
            float n0 = (m0 + u1 + skf[0] * u2) * P[q][0];               \
            float n1 = (m1 + m0 + skf[1] * u1) * P[q][1];               \
            float n2 = (m2 + m1 + skf[2] * m0) * P[q][2];               \
            float n3 = (m3 + m2 + skf[3] * m1) * P[q][3];               \
            float n4 = (m4 + m3 + skf[4] * m2) * P[q][4];               \
            m0 = n0; m1 = n1; m2 = n2; m3 = n3; m4 = n4;                \
        }                                                               \
        float M = fmaxf(fmaxf(fmaxf(m0, m1), fmaxf(m2, m3)), m4);      \
        int eb = __float_as_int(M) >> 23;                               \
        float rs = __int_as_float((254 - eb) << 23);                    \
        m0 *= rs; m1 *= rs; m2 *= rs; m3 *= rs; m4 *= rs;               \
        E = (M > 0.0f) ? (E + eb - 127) : nbE;                          \
    }

    // ---- window 0 (peeled: t=0 consumed by init) ----
    mbar_wait(fmb + 0, 0);                 // full[0] phase 0 (acquire)
    GATHER(&ring[0])
    __syncwarp();
    if (lane == 0) mbar_arrive(emb + 0);   // slot 0 reusable
    if (lane == 0) { m0 = P[0][0]; m1 = P[0][1]; }   // alpha init at t=0
    HALF(1, 4)
    HALF(4, 8)

    // ---- windows 1..NW-1 ----
    for (int w = 1; w < NW; ++w) {
        const int s = w & (RING - 1);
        mbar_wait(fmb + s * 8, (w >> 2) & 1);   // full[s], phase w/RING (acquire)
        GATHER(&ring[s * WROWS * CC])
        __syncwarp();
        if (lane == 0) mbar_arrive(emb + s * 8);
        HALF(0, 4)
        HALF(4, 8)
    }
#undef HALF
#undef GATHER

    // loss = -ln(alpha[S-2] + alpha[S-1]); S-1=128 -> lane25 m3, S-2=127 -> m2
    float tot = m2 + m3;                                  // frame 2^E
    float lf  = (float)E + log2f(fmaxf(tot, 1e-45f));
    float v   = __shfl_sync(FULLM, lf, (SS - 1) / SPL);
    if (lane == 0) out[b] = -LN2F * v;
}

extern "C" void kernel_launch(void* const* d_in, const int* in_sizes, int n_in,
                              void* d_out, int out_size)
{
    const int*   y_true = (const int*)d_in[0];
    const float* y_pred = (const float*)d_in[1];
    // defensive: swap by size if metadata order differs
    if (n_in >= 2 && in_sizes[0] > in_sizes[1]) {
        y_pred = (const float*)d_in[0];
        y_true = (const int*)d_in[1];
    }
    (void)out_size;
    ctc_warp_kernel<<<BB, 64>>>(y_true, y_pred, (float*)d_out);
}

// round 17
// speedup vs baseline: 1.0291x; 1.0291x over previous
#include <cuda_runtime.h>
#include <cstdint>

#define BB 512
#define TT 1024
#define CC 256
#define LL 64
#define SS 129          // 2*LL+1
#define SPL 5           // states per lane (32*5 = 160 >= 129, padded)
#define WROWS 8         // rows per memory window
#define NW (TT / WROWS) // 128 windows
#define RING 4          // ring depth in windows (32 KB SMEM)
#define PREF 3          // prefetch distance (windows)
#define EPSF 1e-7f
#define LN2F 0.69314718055994530942f
#define FULLM 0xffffffffu

__device__ __forceinline__ void cpa16(uint32_t dst, const float* src) {
    asm volatile("cp.async.cg.shared.global [%0], [%1], 16;" :: "r"(dst), "l"(src) : "memory");
}
__device__ __forceinline__ void cpcommit() {
    asm volatile("cp.async.commit_group;" ::: "memory");
}
__device__ __forceinline__ void cpwait2() {
    asm volatile("cp.async.wait_group 2;" ::: "memory");
}

__global__ void __launch_bounds__(64)
ctc_warp_kernel(const int* __restrict__ y_true,
                const float* __restrict__ y_pred,
                float* __restrict__ out)
{
    __shared__ float ring[RING * WROWS * CC];   // 32 KB

    const int b     = blockIdx.x;
    const int tid   = threadIdx.x;
    const int lane  = tid & 31;
    const int wrp   = tid >> 5;
    const int blank = CC - 1;

    if (wrp == 1) {
        // ============ producer warp: owns ALL global->shared traffic ============
        // Each lane covers 8 floats (32 B) of every 256-float row -> TWO 16B
        // cp.async, fully coalesced across lanes (8x 128B lines per row).
        const float* gsrc = y_pred + (size_t)b * (size_t)(TT * CC) + lane * 8;
        uint32_t sl = (uint32_t)__cvta_generic_to_shared(&ring[0]) + lane * 32u;

        // prefill windows 0..PREF-1 (slots 0..2), one commit group per window
#pragma unroll
        for (int w0 = 0; w0 < PREF; w0++) {
#pragma unroll
            for (int r = 0; r < WROWS; r++) {
                uint32_t dst = sl + (uint32_t)((w0 * WROWS + r) * CC) * 4u;
                cpa16(dst,      gsrc + r * CC);
                cpa16(dst + 16, gsrc + r * CC + 4);
            }
            gsrc += WROWS * CC;
            cpcommit();
        }

        // Invariant: 3 groups pending before each wait; wait(2) retires window w.
        // Overwrite of slot (w+PREF)%RING == (w-1)%RING happens after bar_w; the
        // consumer finished reading slot (w-1)%RING before arriving at bar_{w-1}.
        for (int w = 0; w < NW; ++w) {
            cpwait2();            // window w landed
            __syncthreads();      // bar_w: release consumer on window w
            if (w + PREF < NW) {
                uint32_t dst0 = sl + (uint32_t)(((w + PREF) % RING) * WROWS * CC) * 4u;
#pragma unroll
                for (int r = 0; r < WROWS; r++) {
                    uint32_t dst = dst0 + (uint32_t)(r * CC) * 4u;
                    cpa16(dst,      gsrc + r * CC);
                    cpa16(dst + 16, gsrc + r * CC + 4);
                }
                gsrc += WROWS * CC;
            }
            cpcommit();           // unconditional: uniform group accounting
        }
        return;
    }

    // ============ consumer warp: recursion only ============
    int   cls[SPL];
    float skf[SPL];     // 1 if skip (s-2 -> s) allowed, 0 otherwise
#pragma unroll
    for (int j = 0; j < SPL; j++) {
        int s = lane * SPL + j;
        int c = blank, c2 = blank;
        if (s < SS && (s & 1)) {
            c = y_true[b * LL + (s >> 1)];
            if (s >= 3) c2 = y_true[b * LL + (s >> 1) - 1];
        }
        cls[j] = c;
        skf[j] = (c != blank && c != c2) ? 1.0f : 0.0f;
    }

    // block-floating-point state: alpha = m * 2^E (per-lane frame)
    float m0 = 0.f, m1 = 0.f, m2 = 0.f, m3 = 0.f, m4 = 0.f;
    int   E  = 0;
    float P[WROWS][SPL];

    // 4 recursion steps + one renorm; sn carries both the frame alignment and
    // the lane-0 boundary (sn=0 kills the out-of-warp neighbor terms).
#define HALF(QS, QE)                                                    \
    {                                                                   \
        int nbE = __shfl_up_sync(FULLM, E, 1);                          \
        if (lane == 0) nbE = E;                                         \
        int d_ = nbE - E;                                               \
        d_ = d_ < -96 ? -96 : (d_ > 96 ? 96 : d_);                      \
        float sn = __int_as_float((d_ + 127) << 23);                    \
        if (lane == 0) sn = 0.0f;                                       \
        _Pragma("unroll")                                               \
        for (int q = (QS); q < (QE); ++q) {                             \
            float nb4 = __shfl_up_sync(FULLM, m4, 1);                   \
            float nb3 = __shfl_up_sync(FULLM, m3, 1);                   \
            float u1 = nb4 * sn;                                        \
            float u2 = nb3 * sn;                                        \
            float n0 = (m0 + u1 + skf[0] * u2) * P[q][0];               \
            float n1 = (m1 + m0 + skf[1] * u1) * P[q][1];               \
            float n2 = (m2 + m1 + skf[2] * m0) * P[q][2];               \
            float n3 = (m3 + m2 + skf[3] * m1) * P[q][3];               \
            float n4 = (m4 + m3 + skf[4] * m2) * P[q][4];               \
            m0 = n0; m1 = n1; m2 = n2; m3 = n3; m4 = n4;                \
        }                                                               \
        float M = fmaxf(fmaxf(fmaxf(m0, m1), fmaxf(m2, m3)), m4);      \
        int eb = __float_as_int(M) >> 23;                               \
        float rs = __int_as_float((254 - eb) << 23);                    \
        m0 *= rs; m1 *= rs; m2 *= rs; m3 *= rs; m4 *= rs;               \
        E = (M > 0.0f) ? (E + eb - 127) : nbE;                          \
    }

    // ---- window 0 (peeled: t=0 consumed by init) ----
    __syncthreads();                      // bar_0
#pragma unroll
    for (int r = 0; r < WROWS; r++)
#pragma unroll
        for (int j = 0; j < SPL; j++)
            P[r][j] = ring[r * CC + cls[j]] + EPSF;
    if (lane == 0) { m0 = P[0][0]; m1 = P[0][1]; }   // alpha init at t=0
    HALF(1, 4)
    HALF(4, 8)

    // ---- windows 1..NW-1 ----
    for (int w = 1; w < NW; ++w) {
        __syncthreads();                  // bar_w: window w ready
        const float* rb = &ring[(w & (RING - 1)) * WROWS * CC];
#pragma unroll
        for (int r = 0; r < WROWS; r++)
#pragma unroll
            for (int j = 0; j < SPL; j++)
                P[r][j] = rb[r * CC + cls[j]] + EPSF;
        HALF(0, 4)
        HALF(4, 8)
    }
#undef HALF

    // loss = -ln(alpha[S-2] + alpha[S-1]); S-1=128 -> lane25 m3, S-2=127 -> m2
    float tot = m2 + m3;                                  // frame 2^E
    float lf  = (float)E + log2f(fmaxf(tot, 1e-45f));
    float v   = __shfl_sync(FULLM, lf, (SS - 1) / SPL);
    if (lane == 0) out[b] = -LN2F * v;
}

extern "C" void kernel_launch(void* const* d_in, const int* in_sizes, int n_in,
                              void* d_out, int out_size)
{
    const int*   y_true = (const int*)d_in[0];
    const float* y_pred = (const float*)d_in[1];
    // defensive: swap by size if metadata order differs
    if (n_in >= 2 && in_sizes[0] > in_sizes[1]) {
        y_pred = (const float*)d_in[0];
        y_true = (const int*)d_in[1];
    }
    (void)out_size;
    ctc_warp_kernel<<<BB, 64>>>(y_true, y_pred, (float*)d_out);
}